// round 11
// baseline (speedup 1.0000x reference)
#include <cuda_runtime.h>
#include <cstdint>

#define DIMS 2048
#define NCLS 4000
#define NROWS 32768
#define NTHR 128            // 4 warps; 8 blocks/SM at 64 regs
#define NW   (NTHR / 32)
#define MOM 0.9f
#define EPS 1e-12f
#define CAP 64   // per-class bucket capacity; P(Poisson(8.2) > 64) ~ 1e-40

// Graph-safe __device__ scratch (no allocs). g_icnt is zero at module load and
// re-zeroed by gather_finalize after each use -> clean state per launch/replay.
__device__ int g_icnt[2][NCLS];
__device__ int g_rowlist[2][NCLS][CAP];

// Packed two-value block reduction: warp shfl -> smem partials -> single sync
// -> every thread sums the NW warp partials itself. 2 barriers total.
__device__ __forceinline__ float2 blockReduceSum2(float2 v, float2* sh2) {
    int lane = threadIdx.x & 31;
    int w = threadIdx.x >> 5;
    #pragma unroll
    for (int o = 16; o > 0; o >>= 1) {
        v.x += __shfl_xor_sync(0xffffffffu, v.x, o);
        v.y += __shfl_xor_sync(0xffffffffu, v.y, o);
    }
    if (lane == 0) sh2[w] = v;
    __syncthreads();
    float2 r = make_float2(0.f, 0.f);
    #pragma unroll
    for (int i = 0; i < NW; ++i) { r.x += sh2[i].x; r.y += sh2[i].y; }
    __syncthreads();   // sh2 reusable afterwards
    return r;
}

// --------------------------------------------- single-pass hist + bucket
__global__ void fill(const int* __restrict__ idv, const int* __restrict__ idr) {
    int m = blockIdx.y;
    int i = blockIdx.x * blockDim.x + threadIdx.x;
    if (i < NROWS) {
        int id = (m == 0 ? idv : idr)[i];
        int pos = atomicAdd(&g_icnt[m][id], 1);
        if (pos < CAP) g_rowlist[m][id][pos] = i;
    }
}

__device__ __forceinline__ float sumsq4(float4 a) {
    return a.x*a.x + a.y*a.y + a.z*a.z + a.w*a.w;
}

// ------------------------------------------- fused gather + finalize
// One block (128 thr) per (class, modality). Rows processed in pairs with a
// register-held prefetched pair; each thread covers 4 float4 per row.
__global__ __launch_bounds__(NTHR, 8) void gather_finalize(
    const float* __restrict__ fv, const float* __restrict__ fr,
    const float* __restrict__ vism, const float* __restrict__ irm,
    float* __restrict__ out)
{
    __shared__ float2 sh2[NW];
    __shared__ int sh_rows[CAP];
    const int m = blockIdx.y;
    const int c = blockIdx.x;
    const int t = threadIdx.x;

    const float* feat = (m == 0 ? fv : fr);
    const int rawcnt = g_icnt[m][c];          // read by ALL threads
    const int cnt = (rawcnt < CAP) ? rawcnt : CAP;

    if (t < CAP && t < cnt) sh_rows[t] = g_rowlist[m][c][t];
    __syncthreads();

    float4 acc0 = make_float4(0.f, 0.f, 0.f, 0.f);
    float4 acc1 = make_float4(0.f, 0.f, 0.f, 0.f);
    float4 acc2 = make_float4(0.f, 0.f, 0.f, 0.f);
    float4 acc3 = make_float4(0.f, 0.f, 0.f, 0.f);

    // current pair (8 float4) + prefetched next pair (8 float4)
    float4 a0, a1, a2, a3, b0, b1, b2, b3;
    float4 na0, na1, na2, na3, nb0, nb1, nb2, nb3;

    #define LOADROW(idx, X0, X1, X2, X3) do {                               \
        const float4* _f4 = reinterpret_cast<const float4*>(               \
            feat + (size_t)sh_rows[(idx)] * DIMS);                         \
        X0 = __ldcs(&_f4[t]);            X1 = __ldcs(&_f4[t + NTHR]);      \
        X2 = __ldcs(&_f4[t + 2*NTHR]);   X3 = __ldcs(&_f4[t + 3*NTHR]);    \
    } while (0)

    if (cnt > 0) LOADROW(0, a0, a1, a2, a3);
    if (cnt > 1) LOADROW(1, b0, b1, b2, b3);

    const int npairs = cnt >> 1;
    for (int p = 0; p < npairs; ++p) {
        const int base = 2 * p;
        if (base + 2 < cnt) LOADROW(base + 2, na0, na1, na2, na3);
        if (base + 3 < cnt) LOADROW(base + 3, nb0, nb1, nb2, nb3);

        float2 ss = make_float2(sumsq4(a0) + sumsq4(a1) + sumsq4(a2) + sumsq4(a3),
                                sumsq4(b0) + sumsq4(b1) + sumsq4(b2) + sumsq4(b3));
        ss = blockReduceSum2(ss, sh2);
        const float s0 = 1.f / fmaxf(sqrtf(ss.x), EPS);
        const float s1 = 1.f / fmaxf(sqrtf(ss.y), EPS);

        acc0.x += s0*a0.x; acc0.y += s0*a0.y; acc0.z += s0*a0.z; acc0.w += s0*a0.w;
        acc1.x += s0*a1.x; acc1.y += s0*a1.y; acc1.z += s0*a1.z; acc1.w += s0*a1.w;
        acc2.x += s0*a2.x; acc2.y += s0*a2.y; acc2.z += s0*a2.z; acc2.w += s0*a2.w;
        acc3.x += s0*a3.x; acc3.y += s0*a3.y; acc3.z += s0*a3.z; acc3.w += s0*a3.w;
        acc0.x += s1*b0.x; acc0.y += s1*b0.y; acc0.z += s1*b0.z; acc0.w += s1*b0.w;
        acc1.x += s1*b1.x; acc1.y += s1*b1.y; acc1.z += s1*b1.z; acc1.w += s1*b1.w;
        acc2.x += s1*b2.x; acc2.y += s1*b2.y; acc2.z += s1*b2.z; acc2.w += s1*b2.w;
        acc3.x += s1*b3.x; acc3.y += s1*b3.y; acc3.z += s1*b3.z; acc3.w += s1*b3.w;

        a0 = na0; a1 = na1; a2 = na2; a3 = na3;
        b0 = nb0; b1 = nb1; b2 = nb2; b3 = nb3;
    }
    if (cnt & 1) {
        // last (odd) row sits in a*: loaded at init (cnt==1) or via prefetch.
        float2 ss = make_float2(sumsq4(a0) + sumsq4(a1) + sumsq4(a2) + sumsq4(a3), 0.f);
        ss = blockReduceSum2(ss, sh2);
        const float s0 = 1.f / fmaxf(sqrtf(ss.x), EPS);
        acc0.x += s0*a0.x; acc0.y += s0*a0.y; acc0.z += s0*a0.z; acc0.w += s0*a0.w;
        acc1.x += s0*a1.x; acc1.y += s0*a1.y; acc1.z += s0*a1.z; acc1.w += s0*a1.w;
        acc2.x += s0*a2.x; acc2.y += s0*a2.y; acc2.z += s0*a2.z; acc2.w += s0*a2.w;
        acc3.x += s0*a3.x; acc3.y += s0*a3.y; acc3.z += s0*a3.z; acc3.w += s0*a3.w;
    }
    #undef LOADROW

    // Memory row loaded AFTER the gather loop (keeps loop registers lean).
    const float4* m4 = reinterpret_cast<const float4*>(
        (m == 0 ? vism : irm) + (size_t)c * DIMS);
    float4 w0 = __ldcs(&m4[t]);
    float4 w1 = __ldcs(&m4[t + NTHR]);
    float4 w2 = __ldcs(&m4[t + 2*NTHR]);
    float4 w3 = __ldcs(&m4[t + 3*NTHR]);

    const float invc = 1.f / fmaxf((float)cnt, 1.f);
    acc0.x *= invc; acc0.y *= invc; acc0.z *= invc; acc0.w *= invc;
    acc1.x *= invc; acc1.y *= invc; acc1.z *= invc; acc1.w *= invc;
    acc2.x *= invc; acc2.y *= invc; acc2.z *= invc; acc2.w *= invc;
    acc3.x *= invc; acc3.y *= invc; acc3.z *= invc; acc3.w *= invc;

    float2 ssm = blockReduceSum2(make_float2(
        sumsq4(acc0) + sumsq4(acc1) + sumsq4(acc2) + sumsq4(acc3), 0.f), sh2);
    if (t == 0) g_icnt[m][c] = 0;    // safe: all cnt reads happened pre-barrier
    const float inm = 1.f / fmaxf(sqrtf(ssm.x), EPS);

    float4 t0, t1, t2, t3;
    #define BLEND(T, W, A) do {                                             \
        T.x = MOM * W.x + (1.f - MOM) * (A.x * inm);                        \
        T.y = MOM * W.y + (1.f - MOM) * (A.y * inm);                        \
        T.z = MOM * W.z + (1.f - MOM) * (A.z * inm);                        \
        T.w = MOM * W.w + (1.f - MOM) * (A.w * inm);                        \
    } while (0)
    BLEND(t0, w0, acc0); BLEND(t1, w1, acc1);
    BLEND(t2, w2, acc2); BLEND(t3, w3, acc3);
    #undef BLEND

    float2 sst = blockReduceSum2(make_float2(
        sumsq4(t0) + sumsq4(t1) + sumsq4(t2) + sumsq4(t3), 0.f), sh2);
    const float int_ = 1.f / fmaxf(sqrtf(sst.x), EPS);

    const bool present = (cnt > 0);
    float4 o0, o1, o2, o3;
    #define SEL(O, T, W) do {                                               \
        O.x = present ? T.x * int_ : W.x;                                   \
        O.y = present ? T.y * int_ : W.y;                                   \
        O.z = present ? T.z * int_ : W.z;                                   \
        O.w = present ? T.w * int_ : W.w;                                   \
    } while (0)
    SEL(o0, t0, w0); SEL(o1, t1, w1); SEL(o2, t2, w2); SEL(o3, t3, w3);
    #undef SEL

    float4* o4 = reinterpret_cast<float4*>(
        out + (size_t)m * NCLS * DIMS + (size_t)c * DIMS);
    __stcs(&o4[t], o0);
    __stcs(&o4[t + NTHR], o1);
    __stcs(&o4[t + 2*NTHR], o2);
    __stcs(&o4[t + 3*NTHR], o3);
}

extern "C" void kernel_launch(void* const* d_in, const int* in_sizes, int n_in,
                              void* d_out, int out_size) {
    const float* fv   = (const float*)d_in[0];
    const float* fr   = (const float*)d_in[1];
    const int*   idv  = (const int*)d_in[2];
    const int*   idr  = (const int*)d_in[3];
    const float* vism = (const float*)d_in[4];
    const float* irm  = (const float*)d_in[5];
    float* out = (float*)d_out;

    fill<<<dim3((NROWS + 255) / 256, 2), 256>>>(idv, idr);
    gather_finalize<<<dim3(NCLS, 2), NTHR>>>(fv, fr, vism, irm, out);
}

// round 12
// speedup vs baseline: 1.0115x; 1.0115x over previous
#include <cuda_runtime.h>
#include <cstdint>

#define DIMS 2048
#define NCLS 4000
#define NROWS 32768
#define NTHR 128            // 4 warps; 8 blocks/SM at 64 regs
#define NW   (NTHR / 32)
#define MOM 0.9f
#define EPS 1e-12f
#define CAP 64   // per-class bucket capacity; P(Poisson(8.2) > 64) ~ 1e-40

// Graph-safe __device__ scratch (no allocs). g_icnt is zero at module load and
// re-zeroed by gather_finalize after each use -> clean state per launch/replay.
__device__ int g_icnt[2][NCLS];
__device__ int g_rowlist[2][NCLS][CAP];

// Packed two-value block reduction: warp shfl -> smem partials -> single sync
// -> every thread sums the NW warp partials itself. 2 barriers total.
__device__ __forceinline__ float2 blockReduceSum2(float2 v, float2* sh2) {
    int lane = threadIdx.x & 31;
    int w = threadIdx.x >> 5;
    #pragma unroll
    for (int o = 16; o > 0; o >>= 1) {
        v.x += __shfl_xor_sync(0xffffffffu, v.x, o);
        v.y += __shfl_xor_sync(0xffffffffu, v.y, o);
    }
    if (lane == 0) sh2[w] = v;
    __syncthreads();
    float2 r = make_float2(0.f, 0.f);
    #pragma unroll
    for (int i = 0; i < NW; ++i) { r.x += sh2[i].x; r.y += sh2[i].y; }
    __syncthreads();   // sh2 reusable afterwards
    return r;
}

// --------------------------------------------- single-pass hist + bucket
__global__ void fill(const int* __restrict__ idv, const int* __restrict__ idr) {
    int m = blockIdx.y;
    int i = blockIdx.x * blockDim.x + threadIdx.x;
    if (i < NROWS) {
        int id = (m == 0 ? idv : idr)[i];
        int pos = atomicAdd(&g_icnt[m][id], 1);
        if (pos < CAP) g_rowlist[m][id][pos] = i;
    }
}

__device__ __forceinline__ float sumsq4(float4 a) {
    return a.x*a.x + a.y*a.y + a.z*a.z + a.w*a.w;
}

// ------------------------------------------- fused gather + finalize
// One block (128 thr) per (class, modality). Rows processed in pairs with a
// register-held prefetched pair; each thread covers 4 float4 per row.
__global__ __launch_bounds__(NTHR, 8) void gather_finalize(
    const float* __restrict__ fv, const float* __restrict__ fr,
    const float* __restrict__ vism, const float* __restrict__ irm,
    float* __restrict__ out)
{
    __shared__ float2 sh2[NW];
    __shared__ int sh_rows[CAP];
    const int m = blockIdx.y;
    const int c = blockIdx.x;
    const int t = threadIdx.x;

    const float* feat = (m == 0 ? fv : fr);
    const int rawcnt = g_icnt[m][c];          // read by ALL threads
    const int cnt = (rawcnt < CAP) ? rawcnt : CAP;

    if (t < CAP && t < cnt) sh_rows[t] = g_rowlist[m][c][t];
    __syncthreads();

    float4 acc0 = make_float4(0.f, 0.f, 0.f, 0.f);
    float4 acc1 = make_float4(0.f, 0.f, 0.f, 0.f);
    float4 acc2 = make_float4(0.f, 0.f, 0.f, 0.f);
    float4 acc3 = make_float4(0.f, 0.f, 0.f, 0.f);

    // current pair (8 float4) + prefetched next pair (8 float4)
    float4 a0, a1, a2, a3, b0, b1, b2, b3;
    float4 na0, na1, na2, na3, nb0, nb1, nb2, nb3;

    #define LOADROW(idx, X0, X1, X2, X3) do {                               \
        const float4* _f4 = reinterpret_cast<const float4*>(               \
            feat + (size_t)sh_rows[(idx)] * DIMS);                         \
        X0 = __ldcs(&_f4[t]);            X1 = __ldcs(&_f4[t + NTHR]);      \
        X2 = __ldcs(&_f4[t + 2*NTHR]);   X3 = __ldcs(&_f4[t + 3*NTHR]);    \
    } while (0)

    if (cnt > 0) LOADROW(0, a0, a1, a2, a3);
    if (cnt > 1) LOADROW(1, b0, b1, b2, b3);

    const int npairs = cnt >> 1;
    for (int p = 0; p < npairs; ++p) {
        const int base = 2 * p;
        if (base + 2 < cnt) LOADROW(base + 2, na0, na1, na2, na3);
        if (base + 3 < cnt) LOADROW(base + 3, nb0, nb1, nb2, nb3);

        float2 ss = make_float2(sumsq4(a0) + sumsq4(a1) + sumsq4(a2) + sumsq4(a3),
                                sumsq4(b0) + sumsq4(b1) + sumsq4(b2) + sumsq4(b3));
        ss = blockReduceSum2(ss, sh2);
        const float s0 = 1.f / fmaxf(sqrtf(ss.x), EPS);
        const float s1 = 1.f / fmaxf(sqrtf(ss.y), EPS);

        acc0.x += s0*a0.x; acc0.y += s0*a0.y; acc0.z += s0*a0.z; acc0.w += s0*a0.w;
        acc1.x += s0*a1.x; acc1.y += s0*a1.y; acc1.z += s0*a1.z; acc1.w += s0*a1.w;
        acc2.x += s0*a2.x; acc2.y += s0*a2.y; acc2.z += s0*a2.z; acc2.w += s0*a2.w;
        acc3.x += s0*a3.x; acc3.y += s0*a3.y; acc3.z += s0*a3.z; acc3.w += s0*a3.w;
        acc0.x += s1*b0.x; acc0.y += s1*b0.y; acc0.z += s1*b0.z; acc0.w += s1*b0.w;
        acc1.x += s1*b1.x; acc1.y += s1*b1.y; acc1.z += s1*b1.z; acc1.w += s1*b1.w;
        acc2.x += s1*b2.x; acc2.y += s1*b2.y; acc2.z += s1*b2.z; acc2.w += s1*b2.w;
        acc3.x += s1*b3.x; acc3.y += s1*b3.y; acc3.z += s1*b3.z; acc3.w += s1*b3.w;

        a0 = na0; a1 = na1; a2 = na2; a3 = na3;
        b0 = nb0; b1 = nb1; b2 = nb2; b3 = nb3;
    }
    if (cnt & 1) {
        // last (odd) row sits in a*: loaded at init (cnt==1) or via prefetch.
        float2 ss = make_float2(sumsq4(a0) + sumsq4(a1) + sumsq4(a2) + sumsq4(a3), 0.f);
        ss = blockReduceSum2(ss, sh2);
        const float s0 = 1.f / fmaxf(sqrtf(ss.x), EPS);
        acc0.x += s0*a0.x; acc0.y += s0*a0.y; acc0.z += s0*a0.z; acc0.w += s0*a0.w;
        acc1.x += s0*a1.x; acc1.y += s0*a1.y; acc1.z += s0*a1.z; acc1.w += s0*a1.w;
        acc2.x += s0*a2.x; acc2.y += s0*a2.y; acc2.z += s0*a2.z; acc2.w += s0*a2.w;
        acc3.x += s0*a3.x; acc3.y += s0*a3.y; acc3.z += s0*a3.z; acc3.w += s0*a3.w;
    }
    #undef LOADROW

    // Memory row loaded AFTER the gather loop (keeps loop registers lean).
    const float4* m4 = reinterpret_cast<const float4*>(
        (m == 0 ? vism : irm) + (size_t)c * DIMS);
    float4 w0 = __ldcs(&m4[t]);
    float4 w1 = __ldcs(&m4[t + NTHR]);
    float4 w2 = __ldcs(&m4[t + 2*NTHR]);
    float4 w3 = __ldcs(&m4[t + 3*NTHR]);

    const float invc = 1.f / fmaxf((float)cnt, 1.f);
    acc0.x *= invc; acc0.y *= invc; acc0.z *= invc; acc0.w *= invc;
    acc1.x *= invc; acc1.y *= invc; acc1.z *= invc; acc1.w *= invc;
    acc2.x *= invc; acc2.y *= invc; acc2.z *= invc; acc2.w *= invc;
    acc3.x *= invc; acc3.y *= invc; acc3.z *= invc; acc3.w *= invc;

    float2 ssm = blockReduceSum2(make_float2(
        sumsq4(acc0) + sumsq4(acc1) + sumsq4(acc2) + sumsq4(acc3), 0.f), sh2);
    if (t == 0) g_icnt[m][c] = 0;    // safe: all cnt reads happened pre-barrier
    const float inm = 1.f / fmaxf(sqrtf(ssm.x), EPS);

    float4 t0, t1, t2, t3;
    #define BLEND(T, W, A) do {                                             \
        T.x = MOM * W.x + (1.f - MOM) * (A.x * inm);                        \
        T.y = MOM * W.y + (1.f - MOM) * (A.y * inm);                        \
        T.z = MOM * W.z + (1.f - MOM) * (A.z * inm);                        \
        T.w = MOM * W.w + (1.f - MOM) * (A.w * inm);                        \
    } while (0)
    BLEND(t0, w0, acc0); BLEND(t1, w1, acc1);
    BLEND(t2, w2, acc2); BLEND(t3, w3, acc3);
    #undef BLEND

    float2 sst = blockReduceSum2(make_float2(
        sumsq4(t0) + sumsq4(t1) + sumsq4(t2) + sumsq4(t3), 0.f), sh2);
    const float int_ = 1.f / fmaxf(sqrtf(sst.x), EPS);

    const bool present = (cnt > 0);
    float4 o0, o1, o2, o3;
    #define SEL(O, T, W) do {                                               \
        O.x = present ? T.x * int_ : W.x;                                   \
        O.y = present ? T.y * int_ : W.y;                                   \
        O.z = present ? T.z * int_ : W.z;                                   \
        O.w = present ? T.w * int_ : W.w;                                   \
    } while (0)
    SEL(o0, t0, w0); SEL(o1, t1, w1); SEL(o2, t2, w2); SEL(o3, t3, w3);
    #undef SEL

    float4* o4 = reinterpret_cast<float4*>(
        out + (size_t)m * NCLS * DIMS + (size_t)c * DIMS);
    __stcs(&o4[t], o0);
    __stcs(&o4[t + NTHR], o1);
    __stcs(&o4[t + 2*NTHR], o2);
    __stcs(&o4[t + 3*NTHR], o3);
}

extern "C" void kernel_launch(void* const* d_in, const int* in_sizes, int n_in,
                              void* d_out, int out_size) {
    const float* fv   = (const float*)d_in[0];
    const float* fr   = (const float*)d_in[1];
    const int*   idv  = (const int*)d_in[2];
    const int*   idr  = (const int*)d_in[3];
    const float* vism = (const float*)d_in[4];
    const float* irm  = (const float*)d_in[5];
    float* out = (float*)d_out;

    fill<<<dim3((NROWS + 255) / 256, 2), 256>>>(idv, idr);
    gather_finalize<<<dim3(NCLS, 2), NTHR>>>(fv, fr, vism, irm, out);
}

// round 13
// speedup vs baseline: 1.5706x; 1.5526x over previous
#include <cuda_runtime.h>
#include <cstdint>

#define DIMS 2048
#define NCLS 4000
#define NROWS 32768
#define NTHR 256
#define MOM 0.9f
#define EPS 1e-12f
#define CAP 64   // per-class bucket capacity; P(Poisson(8.2) > 64) ~ 1e-40

// Graph-safe __device__ scratch (no allocs). g_icnt is zero at module load and
// re-zeroed by gather_finalize after each use -> clean state per launch/replay.
__device__ int g_icnt[2][NCLS];
__device__ int g_rowlist[2][NCLS][CAP];

// Packed two-value block reduction: warp shfl -> smem partials -> single sync
// -> every thread sums the 8 warp partials itself. 2 barriers total.
__device__ __forceinline__ float2 blockReduceSum2(float2 v, float2* sh2) {
    int lane = threadIdx.x & 31;
    int w = threadIdx.x >> 5;
    #pragma unroll
    for (int o = 16; o > 0; o >>= 1) {
        v.x += __shfl_xor_sync(0xffffffffu, v.x, o);
        v.y += __shfl_xor_sync(0xffffffffu, v.y, o);
    }
    if (lane == 0) sh2[w] = v;
    __syncthreads();
    float2 r = make_float2(0.f, 0.f);
    #pragma unroll
    for (int i = 0; i < NTHR / 32; ++i) { r.x += sh2[i].x; r.y += sh2[i].y; }
    __syncthreads();   // sh2 reusable afterwards
    return r;
}

__device__ __forceinline__ void prefetchL2(const void* p) {
    asm volatile("prefetch.global.L2 [%0];" :: "l"(p));
}

// --------------------------------------------- single-pass hist + bucket
__global__ void fill(const int* __restrict__ idv, const int* __restrict__ idr) {
    int m = blockIdx.y;
    int i = blockIdx.x * blockDim.x + threadIdx.x;
    if (i < NROWS) {
        int id = (m == 0 ? idv : idr)[i];
        int pos = atomicAdd(&g_icnt[m][id], 1);
        if (pos < CAP) g_rowlist[m][id][pos] = i;
    }
}

__device__ __forceinline__ float sumsq8(float4 a, float4 b) {
    return a.x*a.x + a.y*a.y + a.z*a.z + a.w*a.w
         + b.x*b.x + b.y*b.y + b.z*b.z + b.w*b.w;
}

// ------------------------------------------- fused gather + finalize
// One block per (class, modality). Rows in pairs: register-held current pair +
// register-prefetched next pair + L2-prefetched next-next pair.
__global__ __launch_bounds__(NTHR, 4) void gather_finalize(
    const float* __restrict__ fv, const float* __restrict__ fr,
    const float* __restrict__ vism, const float* __restrict__ irm,
    float* __restrict__ out)
{
    __shared__ float2 sh2[NTHR / 32];
    __shared__ int sh_rows[CAP];
    const int m = blockIdx.y;
    const int c = blockIdx.x;
    const int t = threadIdx.x;

    const float* feat = (m == 0 ? fv : fr);
    const int rawcnt = g_icnt[m][c];          // read by ALL threads
    const int cnt = (rawcnt < CAP) ? rawcnt : CAP;

    if (t < CAP && t < cnt) sh_rows[t] = g_rowlist[m][c][t];
    __syncthreads();

    float4 acc0 = make_float4(0.f, 0.f, 0.f, 0.f);
    float4 acc1 = make_float4(0.f, 0.f, 0.f, 0.f);

    // current pair + register-prefetched next pair
    float4 a0, b0, a1, b1, na0, nb0, na1, nb1;

    #define LOADROW(idx, X, Y) do {                                        \
        const float4* _f4 = reinterpret_cast<const float4*>(               \
            feat + (size_t)sh_rows[(idx)] * DIMS);                         \
        X = __ldcs(&_f4[t]); Y = __ldcs(&_f4[t + NTHR]);                   \
    } while (0)

    // L2-prefetch one full row (8 KB = 64 lines of 128B) using threads
    // [woff*64, woff*64+64). Rows alternate warp groups to spread issue.
    #define PREFROW(idx, woff) do {                                        \
        const char* _p = reinterpret_cast<const char*>(                    \
            feat + (size_t)sh_rows[(idx)] * DIMS);                         \
        int _r = t - (woff) * 64;                                          \
        if (_r >= 0 && _r < 64) prefetchL2(_p + _r * 128);                 \
    } while (0)

    if (cnt > 0) LOADROW(0, a0, b0);
    if (cnt > 1) LOADROW(1, a1, b1);
    if (cnt > 2) PREFROW(2, 0);
    if (cnt > 3) PREFROW(3, 1);

    const int npairs = cnt >> 1;
    for (int p = 0; p < npairs; ++p) {
        const int base = 2 * p;
        if (base + 2 < cnt) LOADROW(base + 2, na0, nb0);
        if (base + 3 < cnt) LOADROW(base + 3, na1, nb1);
        // L2-prefetch the pair after that (zero register cost).
        if (base + 4 < cnt) PREFROW(base + 4, 0);
        if (base + 5 < cnt) PREFROW(base + 5, 1);

        float2 ss = make_float2(sumsq8(a0, b0), sumsq8(a1, b1));
        ss = blockReduceSum2(ss, sh2);
        const float s0 = 1.f / fmaxf(sqrtf(ss.x), EPS);
        const float s1 = 1.f / fmaxf(sqrtf(ss.y), EPS);

        acc0.x += s0 * a0.x; acc0.y += s0 * a0.y; acc0.z += s0 * a0.z; acc0.w += s0 * a0.w;
        acc1.x += s0 * b0.x; acc1.y += s0 * b0.y; acc1.z += s0 * b0.z; acc1.w += s0 * b0.w;
        acc0.x += s1 * a1.x; acc0.y += s1 * a1.y; acc0.z += s1 * a1.z; acc0.w += s1 * a1.w;
        acc1.x += s1 * b1.x; acc1.y += s1 * b1.y; acc1.z += s1 * b1.z; acc1.w += s1 * b1.w;

        a0 = na0; b0 = nb0; a1 = na1; b1 = nb1;
    }
    if (cnt & 1) {
        // last (odd) row: loaded at init (cnt==1) or via the base+2 prefetch.
        float2 ss = make_float2(sumsq8(a0, b0), 0.f);
        ss = blockReduceSum2(ss, sh2);
        const float s0 = 1.f / fmaxf(sqrtf(ss.x), EPS);
        acc0.x += s0 * a0.x; acc0.y += s0 * a0.y; acc0.z += s0 * a0.z; acc0.w += s0 * a0.w;
        acc1.x += s0 * b0.x; acc1.y += s0 * b0.y; acc1.z += s0 * b0.z; acc1.w += s0 * b0.w;
    }
    #undef LOADROW
    #undef PREFROW

    // Memory row loaded AFTER the gather loop (keeps loop registers lean).
    const float4* m4 = reinterpret_cast<const float4*>(
        (m == 0 ? vism : irm) + (size_t)c * DIMS);
    float4 w0 = __ldcs(&m4[t]), w1 = __ldcs(&m4[t + NTHR]);

    const float invc = 1.f / fmaxf((float)cnt, 1.f);
    acc0.x *= invc; acc0.y *= invc; acc0.z *= invc; acc0.w *= invc;
    acc1.x *= invc; acc1.y *= invc; acc1.z *= invc; acc1.w *= invc;

    float2 ssm = blockReduceSum2(make_float2(sumsq8(acc0, acc1), 0.f), sh2);
    if (t == 0) g_icnt[m][c] = 0;    // safe: all cnt reads happened pre-barrier
    const float inm = 1.f / fmaxf(sqrtf(ssm.x), EPS);

    float4 t0, t1;
    t0.x = MOM * w0.x + (1.f - MOM) * (acc0.x * inm);
    t0.y = MOM * w0.y + (1.f - MOM) * (acc0.y * inm);
    t0.z = MOM * w0.z + (1.f - MOM) * (acc0.z * inm);
    t0.w = MOM * w0.w + (1.f - MOM) * (acc0.w * inm);
    t1.x = MOM * w1.x + (1.f - MOM) * (acc1.x * inm);
    t1.y = MOM * w1.y + (1.f - MOM) * (acc1.y * inm);
    t1.z = MOM * w1.z + (1.f - MOM) * (acc1.z * inm);
    t1.w = MOM * w1.w + (1.f - MOM) * (acc1.w * inm);

    float2 sst = blockReduceSum2(make_float2(sumsq8(t0, t1), 0.f), sh2);
    const float int_ = 1.f / fmaxf(sqrtf(sst.x), EPS);

    const bool present = (cnt > 0);
    float4 o0, o1;
    o0.x = present ? t0.x * int_ : w0.x;
    o0.y = present ? t0.y * int_ : w0.y;
    o0.z = present ? t0.z * int_ : w0.z;
    o0.w = present ? t0.w * int_ : w0.w;
    o1.x = present ? t1.x * int_ : w1.x;
    o1.y = present ? t1.y * int_ : w1.y;
    o1.z = present ? t1.z * int_ : w1.z;
    o1.w = present ? t1.w * int_ : w1.w;

    float4* o4 = reinterpret_cast<float4*>(
        out + (size_t)m * NCLS * DIMS + (size_t)c * DIMS);
    __stcs(&o4[t], o0);
    __stcs(&o4[t + NTHR], o1);
}

extern "C" void kernel_launch(void* const* d_in, const int* in_sizes, int n_in,
                              void* d_out, int out_size) {
    const float* fv   = (const float*)d_in[0];
    const float* fr   = (const float*)d_in[1];
    const int*   idv  = (const int*)d_in[2];
    const int*   idr  = (const int*)d_in[3];
    const float* vism = (const float*)d_in[4];
    const float* irm  = (const float*)d_in[5];
    float* out = (float*)d_out;

    fill<<<dim3((NROWS + 255) / 256, 2), 256>>>(idv, idr);
    gather_finalize<<<dim3(NCLS, 2), NTHR>>>(fv, fr, vism, irm, out);
}

// round 14
// speedup vs baseline: 1.6030x; 1.0206x over previous
#include <cuda_runtime.h>
#include <cstdint>

#define DIMS 2048
#define NCLS 4000
#define NROWS 32768
#define NTHR 256
#define MOM 0.9f
#define EPS 1e-12f
#define CAP 64   // per-class bucket capacity; P(Poisson(8.2) > 64) ~ 1e-40

// Graph-safe __device__ scratch (no allocs). g_icnt is zero at module load and
// re-zeroed by gather_finalize after each use -> clean state per launch/replay.
__device__ int g_icnt[2][NCLS];
__device__ int g_rowlist[2][NCLS][CAP];

// Packed two-value block reduction: warp shfl -> smem partials -> single sync
// -> every thread sums the 8 warp partials itself. 2 barriers total.
__device__ __forceinline__ float2 blockReduceSum2(float2 v, float2* sh2) {
    int lane = threadIdx.x & 31;
    int w = threadIdx.x >> 5;
    #pragma unroll
    for (int o = 16; o > 0; o >>= 1) {
        v.x += __shfl_xor_sync(0xffffffffu, v.x, o);
        v.y += __shfl_xor_sync(0xffffffffu, v.y, o);
    }
    if (lane == 0) sh2[w] = v;
    __syncthreads();
    float2 r = make_float2(0.f, 0.f);
    #pragma unroll
    for (int i = 0; i < NTHR / 32; ++i) { r.x += sh2[i].x; r.y += sh2[i].y; }
    __syncthreads();   // sh2 reusable afterwards
    return r;
}

__device__ __forceinline__ void prefetchL2(const void* p) {
    asm volatile("prefetch.global.L2 [%0];" :: "l"(p));
}

// --------------------------------------------- single-pass hist + bucket
__global__ void fill(const int* __restrict__ idv, const int* __restrict__ idr) {
    int m = blockIdx.y;
    int i = blockIdx.x * blockDim.x + threadIdx.x;
    if (i < NROWS) {
        int id = (m == 0 ? idv : idr)[i];
        int pos = atomicAdd(&g_icnt[m][id], 1);
        if (pos < CAP) g_rowlist[m][id][pos] = i;
    }
}

__device__ __forceinline__ float sumsq8(float4 a, float4 b) {
    return a.x*a.x + a.y*a.y + a.z*a.z + a.w*a.w
         + b.x*b.x + b.y*b.y + b.z*b.z + b.w*b.w;
}

// ------------------------------------------- fused gather + finalize
// One block per (class, modality). Rows in pairs: register-held current pair +
// register-prefetched next pair + L2-prefetched pairs two iterations ahead.
// Memory row L2-prefetched at block start, consumed in the epilogue.
__global__ __launch_bounds__(NTHR, 4) void gather_finalize(
    const float* __restrict__ fv, const float* __restrict__ fr,
    const float* __restrict__ vism, const float* __restrict__ irm,
    float* __restrict__ out)
{
    __shared__ float2 sh2[NTHR / 32];
    __shared__ int sh_rows[CAP];
    const int m = blockIdx.y;
    const int c = blockIdx.x;
    const int t = threadIdx.x;

    const float* feat = (m == 0 ? fv : fr);
    const float* memrow = (m == 0 ? vism : irm) + (size_t)c * DIMS;

    // L2-prefetch the memory row now; it's consumed only in the epilogue.
    if (t < 64) prefetchL2(reinterpret_cast<const char*>(memrow) + t * 128);

    const int rawcnt = g_icnt[m][c];          // read by ALL threads
    const int cnt = (rawcnt < CAP) ? rawcnt : CAP;

    if (t < CAP && t < cnt) sh_rows[t] = g_rowlist[m][c][t];
    __syncthreads();

    float4 acc0 = make_float4(0.f, 0.f, 0.f, 0.f);
    float4 acc1 = make_float4(0.f, 0.f, 0.f, 0.f);

    // current pair + register-prefetched next pair
    float4 a0, b0, a1, b1, na0, nb0, na1, nb1;

    #define LOADROW(idx, X, Y) do {                                        \
        const float4* _f4 = reinterpret_cast<const float4*>(               \
            feat + (size_t)sh_rows[(idx)] * DIMS);                         \
        X = __ldcs(&_f4[t]); Y = __ldcs(&_f4[t + NTHR]);                   \
    } while (0)

    // L2-prefetch one full row (8 KB = 64 lines of 128B) using threads
    // [woff*64, woff*64+64). Rows alternate thread groups to spread issue.
    #define PREFROW(idx, woff) do {                                        \
        const char* _p = reinterpret_cast<const char*>(                    \
            feat + (size_t)sh_rows[(idx)] * DIMS);                         \
        int _r = t - (woff) * 64;                                          \
        if (_r >= 0 && _r < 64) prefetchL2(_p + _r * 128);                 \
    } while (0)

    if (cnt > 0) LOADROW(0, a0, b0);
    if (cnt > 1) LOADROW(1, a1, b1);
    // Initial L2 prefetch: two pairs ahead (rows 2..5).
    if (cnt > 2) PREFROW(2, 0);
    if (cnt > 3) PREFROW(3, 1);
    if (cnt > 4) PREFROW(4, 2);
    if (cnt > 5) PREFROW(5, 3);

    const int npairs = cnt >> 1;
    for (int p = 0; p < npairs; ++p) {
        const int base = 2 * p;
        if (base + 2 < cnt) LOADROW(base + 2, na0, nb0);
        if (base + 3 < cnt) LOADROW(base + 3, na1, nb1);
        // L2-prefetch two pairs ahead (zero register cost).
        if (base + 6 < cnt) PREFROW(base + 6, 0);
        if (base + 7 < cnt) PREFROW(base + 7, 1);

        float2 ss = make_float2(sumsq8(a0, b0), sumsq8(a1, b1));
        ss = blockReduceSum2(ss, sh2);
        const float s0 = 1.f / fmaxf(sqrtf(ss.x), EPS);
        const float s1 = 1.f / fmaxf(sqrtf(ss.y), EPS);

        acc0.x += s0 * a0.x; acc0.y += s0 * a0.y; acc0.z += s0 * a0.z; acc0.w += s0 * a0.w;
        acc1.x += s0 * b0.x; acc1.y += s0 * b0.y; acc1.z += s0 * b0.z; acc1.w += s0 * b0.w;
        acc0.x += s1 * a1.x; acc0.y += s1 * a1.y; acc0.z += s1 * a1.z; acc0.w += s1 * a1.w;
        acc1.x += s1 * b1.x; acc1.y += s1 * b1.y; acc1.z += s1 * b1.z; acc1.w += s1 * b1.w;

        a0 = na0; b0 = nb0; a1 = na1; b1 = nb1;
    }
    if (cnt & 1) {
        // last (odd) row: loaded at init (cnt==1) or via the base+2 prefetch.
        float2 ss = make_float2(sumsq8(a0, b0), 0.f);
        ss = blockReduceSum2(ss, sh2);
        const float s0 = 1.f / fmaxf(sqrtf(ss.x), EPS);
        acc0.x += s0 * a0.x; acc0.y += s0 * a0.y; acc0.z += s0 * a0.z; acc0.w += s0 * a0.w;
        acc1.x += s0 * b0.x; acc1.y += s0 * b0.y; acc1.z += s0 * b0.z; acc1.w += s0 * b0.w;
    }
    #undef LOADROW
    #undef PREFROW

    // Memory row: L2-prefetched at block start -> mostly L2 hits here.
    const float4* m4 = reinterpret_cast<const float4*>(memrow);
    float4 w0 = __ldcs(&m4[t]), w1 = __ldcs(&m4[t + NTHR]);

    const float invc = 1.f / fmaxf((float)cnt, 1.f);
    acc0.x *= invc; acc0.y *= invc; acc0.z *= invc; acc0.w *= invc;
    acc1.x *= invc; acc1.y *= invc; acc1.z *= invc; acc1.w *= invc;

    float2 ssm = blockReduceSum2(make_float2(sumsq8(acc0, acc1), 0.f), sh2);
    if (t == 0) g_icnt[m][c] = 0;    // safe: all cnt reads happened pre-barrier
    const float inm = 1.f / fmaxf(sqrtf(ssm.x), EPS);

    float4 t0, t1;
    t0.x = MOM * w0.x + (1.f - MOM) * (acc0.x * inm);
    t0.y = MOM * w0.y + (1.f - MOM) * (acc0.y * inm);
    t0.z = MOM * w0.z + (1.f - MOM) * (acc0.z * inm);
    t0.w = MOM * w0.w + (1.f - MOM) * (acc0.w * inm);
    t1.x = MOM * w1.x + (1.f - MOM) * (acc1.x * inm);
    t1.y = MOM * w1.y + (1.f - MOM) * (acc1.y * inm);
    t1.z = MOM * w1.z + (1.f - MOM) * (acc1.z * inm);
    t1.w = MOM * w1.w + (1.f - MOM) * (acc1.w * inm);

    float2 sst = blockReduceSum2(make_float2(sumsq8(t0, t1), 0.f), sh2);
    const float int_ = 1.f / fmaxf(sqrtf(sst.x), EPS);

    const bool present = (cnt > 0);
    float4 o0, o1;
    o0.x = present ? t0.x * int_ : w0.x;
    o0.y = present ? t0.y * int_ : w0.y;
    o0.z = present ? t0.z * int_ : w0.z;
    o0.w = present ? t0.w * int_ : w0.w;
    o1.x = present ? t1.x * int_ : w1.x;
    o1.y = present ? t1.y * int_ : w1.y;
    o1.z = present ? t1.z * int_ : w1.z;
    o1.w = present ? t1.w * int_ : w1.w;

    float4* o4 = reinterpret_cast<float4*>(
        out + (size_t)m * NCLS * DIMS + (size_t)c * DIMS);
    __stcs(&o4[t], o0);
    __stcs(&o4[t + NTHR], o1);
}

extern "C" void kernel_launch(void* const* d_in, const int* in_sizes, int n_in,
                              void* d_out, int out_size) {
    const float* fv   = (const float*)d_in[0];
    const float* fr   = (const float*)d_in[1];
    const int*   idv  = (const int*)d_in[2];
    const int*   idr  = (const int*)d_in[3];
    const float* vism = (const float*)d_in[4];
    const float* irm  = (const float*)d_in[5];
    float* out = (float*)d_out;

    fill<<<dim3((NROWS + 255) / 256, 2), 256>>>(idv, idr);
    gather_finalize<<<dim3(NCLS, 2), NTHR>>>(fv, fr, vism, irm, out);
}

// round 15
// speedup vs baseline: 1.6156x; 1.0079x over previous
#include <cuda_runtime.h>
#include <cstdint>

#define DIMS 2048
#define NCLS 4000
#define NROWS 32768
#define NTHR 256
#define MOM 0.9f
#define EPS 1e-12f
#define CAP 64   // per-class bucket capacity; P(Poisson(8.2) > 64) ~ 1e-40

// Graph-safe __device__ scratch (no allocs). g_icnt is zero at module load and
// re-zeroed by gather_finalize after each use -> clean state per launch/replay.
__device__ int g_icnt[2][NCLS];
__device__ int g_rowlist[2][NCLS][CAP];

// Packed two-value block reduction: warp shfl -> smem partials -> single sync
// -> every thread sums the 8 warp partials itself. 2 barriers total.
__device__ __forceinline__ float2 blockReduceSum2(float2 v, float2* sh2) {
    int lane = threadIdx.x & 31;
    int w = threadIdx.x >> 5;
    #pragma unroll
    for (int o = 16; o > 0; o >>= 1) {
        v.x += __shfl_xor_sync(0xffffffffu, v.x, o);
        v.y += __shfl_xor_sync(0xffffffffu, v.y, o);
    }
    if (lane == 0) sh2[w] = v;
    __syncthreads();
    float2 r = make_float2(0.f, 0.f);
    #pragma unroll
    for (int i = 0; i < NTHR / 32; ++i) { r.x += sh2[i].x; r.y += sh2[i].y; }
    __syncthreads();   // sh2 reusable afterwards
    return r;
}

__device__ __forceinline__ void prefetchL2(const void* p) {
    asm volatile("prefetch.global.L2 [%0];" :: "l"(p));
}

// --------------------------------------------- single-pass hist + bucket
__global__ void fill(const int* __restrict__ idv, const int* __restrict__ idr) {
    int m = blockIdx.y;
    int i = blockIdx.x * blockDim.x + threadIdx.x;
    if (i < NROWS) {
        int id = (m == 0 ? idv : idr)[i];
        int pos = atomicAdd(&g_icnt[m][id], 1);
        if (pos < CAP) g_rowlist[m][id][pos] = i;
    }
    // Results visible at (implicit) kernel-end membar; let the dependent
    // gather kernel begin its independent prologue now.
    cudaTriggerProgrammaticLaunchCompletion();
}

__device__ __forceinline__ float sumsq8(float4 a, float4 b) {
    return a.x*a.x + a.y*a.y + a.z*a.z + a.w*a.w
         + b.x*b.x + b.y*b.y + b.z*b.z + b.w*b.w;
}

// ------------------------------------------- fused gather + finalize
// One block per (class, modality). Rows in pairs: register-held current pair +
// register-prefetched next pair + L2-prefetched pairs two iterations ahead.
// Memory row L2-prefetched at block start (pre-griddep-sync, overlapping fill).
__global__ __launch_bounds__(NTHR, 4) void gather_finalize(
    const float* __restrict__ fv, const float* __restrict__ fr,
    const float* __restrict__ vism, const float* __restrict__ irm,
    float* __restrict__ out)
{
    __shared__ float2 sh2[NTHR / 32];
    __shared__ int sh_rows[CAP];
    const int m = blockIdx.y;
    const int c = blockIdx.x;
    const int t = threadIdx.x;

    const float* feat = (m == 0 ? fv : fr);
    const float* memrow = (m == 0 ? vism : irm) + (size_t)c * DIMS;

    // Independent prologue: prefetch the epilogue's memory row while the
    // fill kernel may still be running (PDL overlap).
    if (t < 64) prefetchL2(reinterpret_cast<const char*>(memrow) + t * 128);

    // Wait for fill's results before touching g_icnt / g_rowlist.
    cudaGridDependencySynchronize();

    const int rawcnt = g_icnt[m][c];          // read by ALL threads
    const int cnt = (rawcnt < CAP) ? rawcnt : CAP;

    if (t < CAP && t < cnt) sh_rows[t] = g_rowlist[m][c][t];
    __syncthreads();

    float4 acc0 = make_float4(0.f, 0.f, 0.f, 0.f);
    float4 acc1 = make_float4(0.f, 0.f, 0.f, 0.f);

    // current pair + register-prefetched next pair
    float4 a0, b0, a1, b1, na0, nb0, na1, nb1;

    #define LOADROW(idx, X, Y) do {                                        \
        const float4* _f4 = reinterpret_cast<const float4*>(               \
            feat + (size_t)sh_rows[(idx)] * DIMS);                         \
        X = __ldcs(&_f4[t]); Y = __ldcs(&_f4[t + NTHR]);                   \
    } while (0)

    // L2-prefetch one full row (8 KB = 64 lines of 128B) using threads
    // [woff*64, woff*64+64). Rows alternate thread groups to spread issue.
    #define PREFROW(idx, woff) do {                                        \
        const char* _p = reinterpret_cast<const char*>(                    \
            feat + (size_t)sh_rows[(idx)] * DIMS);                         \
        int _r = t - (woff) * 64;                                          \
        if (_r >= 0 && _r < 64) prefetchL2(_p + _r * 128);                 \
    } while (0)

    if (cnt > 0) LOADROW(0, a0, b0);
    if (cnt > 1) LOADROW(1, a1, b1);
    // Initial L2 prefetch: two pairs ahead (rows 2..5).
    if (cnt > 2) PREFROW(2, 0);
    if (cnt > 3) PREFROW(3, 1);
    if (cnt > 4) PREFROW(4, 2);
    if (cnt > 5) PREFROW(5, 3);

    const int npairs = cnt >> 1;
    for (int p = 0; p < npairs; ++p) {
        const int base = 2 * p;
        if (base + 2 < cnt) LOADROW(base + 2, na0, nb0);
        if (base + 3 < cnt) LOADROW(base + 3, na1, nb1);
        // L2-prefetch two pairs ahead (zero register cost).
        if (base + 6 < cnt) PREFROW(base + 6, 0);
        if (base + 7 < cnt) PREFROW(base + 7, 1);

        float2 ss = make_float2(sumsq8(a0, b0), sumsq8(a1, b1));
        ss = blockReduceSum2(ss, sh2);
        const float s0 = 1.f / fmaxf(sqrtf(ss.x), EPS);
        const float s1 = 1.f / fmaxf(sqrtf(ss.y), EPS);

        acc0.x += s0 * a0.x; acc0.y += s0 * a0.y; acc0.z += s0 * a0.z; acc0.w += s0 * a0.w;
        acc1.x += s0 * b0.x; acc1.y += s0 * b0.y; acc1.z += s0 * b0.z; acc1.w += s0 * b0.w;
        acc0.x += s1 * a1.x; acc0.y += s1 * a1.y; acc0.z += s1 * a1.z; acc0.w += s1 * a1.w;
        acc1.x += s1 * b1.x; acc1.y += s1 * b1.y; acc1.z += s1 * b1.z; acc1.w += s1 * b1.w;

        a0 = na0; b0 = nb0; a1 = na1; b1 = nb1;
    }
    if (cnt & 1) {
        // last (odd) row: loaded at init (cnt==1) or via the base+2 prefetch.
        float2 ss = make_float2(sumsq8(a0, b0), 0.f);
        ss = blockReduceSum2(ss, sh2);
        const float s0 = 1.f / fmaxf(sqrtf(ss.x), EPS);
        acc0.x += s0 * a0.x; acc0.y += s0 * a0.y; acc0.z += s0 * a0.z; acc0.w += s0 * a0.w;
        acc1.x += s0 * b0.x; acc1.y += s0 * b0.y; acc1.z += s0 * b0.z; acc1.w += s0 * b0.w;
    }
    #undef LOADROW
    #undef PREFROW

    // Memory row: L2-prefetched at block start -> mostly L2 hits here.
    const float4* m4 = reinterpret_cast<const float4*>(memrow);
    float4 w0 = __ldcs(&m4[t]), w1 = __ldcs(&m4[t + NTHR]);

    const float invc = 1.f / fmaxf((float)cnt, 1.f);
    acc0.x *= invc; acc0.y *= invc; acc0.z *= invc; acc0.w *= invc;
    acc1.x *= invc; acc1.y *= invc; acc1.z *= invc; acc1.w *= invc;

    float2 ssm = blockReduceSum2(make_float2(sumsq8(acc0, acc1), 0.f), sh2);
    if (t == 0) g_icnt[m][c] = 0;    // safe: all cnt reads happened pre-barrier
    const float inm = 1.f / fmaxf(sqrtf(ssm.x), EPS);

    float4 t0, t1;
    t0.x = MOM * w0.x + (1.f - MOM) * (acc0.x * inm);
    t0.y = MOM * w0.y + (1.f - MOM) * (acc0.y * inm);
    t0.z = MOM * w0.z + (1.f - MOM) * (acc0.z * inm);
    t0.w = MOM * w0.w + (1.f - MOM) * (acc0.w * inm);
    t1.x = MOM * w1.x + (1.f - MOM) * (acc1.x * inm);
    t1.y = MOM * w1.y + (1.f - MOM) * (acc1.y * inm);
    t1.z = MOM * w1.z + (1.f - MOM) * (acc1.z * inm);
    t1.w = MOM * w1.w + (1.f - MOM) * (acc1.w * inm);

    float2 sst = blockReduceSum2(make_float2(sumsq8(t0, t1), 0.f), sh2);
    const float int_ = 1.f / fmaxf(sqrtf(sst.x), EPS);

    const bool present = (cnt > 0);
    float4 o0, o1;
    o0.x = present ? t0.x * int_ : w0.x;
    o0.y = present ? t0.y * int_ : w0.y;
    o0.z = present ? t0.z * int_ : w0.z;
    o0.w = present ? t0.w * int_ : w0.w;
    o1.x = present ? t1.x * int_ : w1.x;
    o1.y = present ? t1.y * int_ : w1.y;
    o1.z = present ? t1.z * int_ : w1.z;
    o1.w = present ? t1.w * int_ : w1.w;

    float4* o4 = reinterpret_cast<float4*>(
        out + (size_t)m * NCLS * DIMS + (size_t)c * DIMS);
    __stcs(&o4[t], o0);
    __stcs(&o4[t + NTHR], o1);
}

extern "C" void kernel_launch(void* const* d_in, const int* in_sizes, int n_in,
                              void* d_out, int out_size) {
    const float* fv   = (const float*)d_in[0];
    const float* fr   = (const float*)d_in[1];
    const int*   idv  = (const int*)d_in[2];
    const int*   idr  = (const int*)d_in[3];
    const float* vism = (const float*)d_in[4];
    const float* irm  = (const float*)d_in[5];
    float* out = (float*)d_out;

    fill<<<dim3((NROWS + 255) / 256, 2), 256>>>(idv, idr);

    // Programmatic dependent launch: gather starts while fill drains; it
    // gates on cudaGridDependencySynchronize() before reading fill's output.
    cudaLaunchConfig_t cfg = {};
    cfg.gridDim = dim3(NCLS, 2);
    cfg.blockDim = dim3(NTHR);
    cudaLaunchAttribute attr[1];
    attr[0].id = cudaLaunchAttributeProgrammaticStreamSerialization;
    attr[0].val.programmaticStreamSerializationAllowed = 1;
    cfg.attrs = attr;
    cfg.numAttrs = 1;
    cudaLaunchKernelEx(&cfg, gather_finalize, fv, fr, vism, irm, out);
}